// round 4
// baseline (speedup 1.0000x reference)
#include <cuda_runtime.h>
#include <cuda_bf16.h>
#include <cstdint>
#include <cstddef>

#define ROWS   32768
#define NPROJ  3424
#define CONVD  1792
#define DINNER 1536
#define DMODEL 768

typedef unsigned long long ull;

// ---------------- scratch (device globals; no runtime allocation) ----------------
__device__ float g_A1[(size_t)ROWS * NPROJ];            // zxBCdt
__device__ float g_xc[(size_t)ROWS * CONVD];            // conv+silu output
__device__ float g_y [(size_t)4 * ROWS * DINNER];       // per-direction scan outputs
__device__ __nv_bfloat16 g_Uh [(size_t)ROWS * DMODEL];
__device__ __nv_bfloat16 g_Ul [(size_t)ROWS * DMODEL];
__device__ __nv_bfloat16 g_Wih[(size_t)NPROJ * DMODEL];
__device__ __nv_bfloat16 g_Wil[(size_t)NPROJ * DMODEL];
__device__ __nv_bfloat16 g_Woh[(size_t)DMODEL * DINNER];
__device__ __nv_bfloat16 g_Wol[(size_t)DMODEL * DINNER];
__device__ __nv_bfloat16 g_Yh [(size_t)ROWS * DINNER];
__device__ __nv_bfloat16 g_Yl [(size_t)ROWS * DINNER];

// ---------------- packed f32x2 helpers ----------------
__device__ __forceinline__ ull fma2(ull a, ull b, ull c) {
    ull d; asm("fma.rn.f32x2 %0,%1,%2,%3;" : "=l"(d) : "l"(a), "l"(b), "l"(c)); return d;
}
__device__ __forceinline__ ull mul2(ull a, ull b) {
    ull d; asm("mul.rn.f32x2 %0,%1,%2;" : "=l"(d) : "l"(a), "l"(b)); return d;
}
__device__ __forceinline__ ull add2(ull a, ull b) {
    ull d; asm("add.rn.f32x2 %0,%1,%2;" : "=l"(d) : "l"(a), "l"(b)); return d;
}
__device__ __forceinline__ ull pack2(float x) {
    unsigned r = __float_as_uint(x);
    ull d; asm("mov.b64 %0,{%1,%1};" : "=l"(d) : "r"(r)); return d;
}

// ---------------- fp32 -> bf16 hi/lo split ----------------
__global__ void cvt_kernel(const float* __restrict__ s,
                           __nv_bfloat16* __restrict__ hi,
                           __nv_bfloat16* __restrict__ lo, size_t n) {
    size_t i = (size_t)blockIdx.x * blockDim.x + threadIdx.x;
    if (i >= n) return;
    float v = s[i];
    __nv_bfloat16 h = __float2bfloat16(v);
    hi[i] = h;
    lo[i] = __float2bfloat16(v - __bfloat162float(h));
}

// ---------------- tensor-core GEMM: C[M,N] = A[M,K] * B[N,K]^T (bf16x3, fp32 acc) ----
__device__ __forceinline__ void mma_bf16(float* c, const uint32_t* a, const uint32_t* b) {
    asm volatile("mma.sync.aligned.m16n8k16.row.col.f32.bf16.bf16.f32 "
                 "{%0,%1,%2,%3},{%4,%5,%6,%7},{%8,%9},{%0,%1,%2,%3};"
                 : "+f"(c[0]), "+f"(c[1]), "+f"(c[2]), "+f"(c[3])
                 : "r"(a[0]), "r"(a[1]), "r"(a[2]), "r"(a[3]), "r"(b[0]), "r"(b[1]));
}
__device__ __forceinline__ void ldsm4(uint32_t* r, const __nv_bfloat16* p) {
    uint32_t a = (uint32_t)__cvta_generic_to_shared(p);
    asm volatile("ldmatrix.sync.aligned.m8n8.x4.shared.b16 {%0,%1,%2,%3},[%4];"
                 : "=r"(r[0]), "=r"(r[1]), "=r"(r[2]), "=r"(r[3]) : "r"(a));
}
__device__ __forceinline__ void ldsm2(uint32_t* r, const __nv_bfloat16* p) {
    uint32_t a = (uint32_t)__cvta_generic_to_shared(p);
    asm volatile("ldmatrix.sync.aligned.m8n8.x2.shared.b16 {%0,%1},[%2];"
                 : "=r"(r[0]), "=r"(r[1]) : "r"(a));
}

#define SK 40  // smem row stride (halves): 32 + 8 pad

__global__ void __launch_bounds__(256)
gemm_bf16x3(const __nv_bfloat16* __restrict__ Ah, const __nv_bfloat16* __restrict__ Al,
            const __nv_bfloat16* __restrict__ Bh, const __nv_bfloat16* __restrict__ Bl,
            float* __restrict__ C, int M, int N, int K)
{
    __shared__ __nv_bfloat16 sAh[128 * SK], sAl[128 * SK], sBh[128 * SK], sBl[128 * SK];
    const int tid = threadIdx.x, lane = tid & 31, warp = tid >> 5;
    const int wm = warp >> 2, wn = warp & 3;       // 2x4 warp grid; warp tile 64m x 32n
    const int g = lane >> 2, tg = lane & 3;
    const int mBase = blockIdx.y * 128, nBase = blockIdx.x * 128;

    float acc[4][4][4];
#pragma unroll
    for (int mi = 0; mi < 4; mi++)
#pragma unroll
        for (int ni = 0; ni < 4; ni++)
#pragma unroll
            for (int q = 0; q < 4; q++) acc[mi][ni][q] = 0.f;

    const int row0 = tid >> 2;          // 0..63
    const int seg0 = (tid & 3) * 8;     // half offset within 32-wide k tile
    uint4 rAh[2], rAl[2], rBh[2], rBl[2];

    const int KT = K / 32;
    for (int kt = 0; kt < KT; kt++) {
        // ---- global loads for this k-tile ----
        const int k0 = kt * 32;
#pragma unroll
        for (int rep = 0; rep < 2; rep++) {
            int row = row0 + rep * 64;
            size_t aoff = (size_t)(mBase + row) * K + k0 + seg0;
            rAh[rep] = *(const uint4*)(Ah + aoff);
            rAl[rep] = *(const uint4*)(Al + aoff);
            int brow = nBase + row;
            if (brow < N) {
                size_t boff = (size_t)brow * K + k0 + seg0;
                rBh[rep] = *(const uint4*)(Bh + boff);
                rBl[rep] = *(const uint4*)(Bl + boff);
            } else {
                rBh[rep] = make_uint4(0, 0, 0, 0);
                rBl[rep] = make_uint4(0, 0, 0, 0);
            }
        }
        __syncthreads();
#pragma unroll
        for (int rep = 0; rep < 2; rep++) {
            int row = row0 + rep * 64;
            *(uint4*)&sAh[row * SK + seg0] = rAh[rep];
            *(uint4*)&sAl[row * SK + seg0] = rAl[rep];
            *(uint4*)&sBh[row * SK + seg0] = rBh[rep];
            *(uint4*)&sBl[row * SK + seg0] = rBl[rep];
        }
        __syncthreads();

        // ---- compute: two k16 steps ----
#pragma unroll
        for (int kk = 0; kk < 32; kk += 16) {
            uint32_t aH[4][4], aL[4][4], bH[4][2], bL[4][2];
#pragma unroll
            for (int mi = 0; mi < 4; mi++) {
                int off = (wm * 64 + mi * 16 + (lane & 15)) * SK + kk + ((lane >> 4) << 3);
                ldsm4(aH[mi], &sAh[off]);
                ldsm4(aL[mi], &sAl[off]);
            }
#pragma unroll
            for (int ni = 0; ni < 4; ni++) {
                int off = (wn * 32 + ni * 8 + (lane & 7)) * SK + kk + (((lane >> 3) & 1) << 3);
                ldsm2(bH[ni], &sBh[off]);
                ldsm2(bL[ni], &sBl[off]);
            }
#pragma unroll
            for (int mi = 0; mi < 4; mi++)
#pragma unroll
                for (int ni = 0; ni < 4; ni++) {
                    mma_bf16(acc[mi][ni], aH[mi], bH[ni]);
                    mma_bf16(acc[mi][ni], aL[mi], bH[ni]);
                    mma_bf16(acc[mi][ni], aH[mi], bL[ni]);
                }
        }
    }

    // ---- epilogue ----
#pragma unroll
    for (int mi = 0; mi < 4; mi++)
#pragma unroll
        for (int ni = 0; ni < 4; ni++) {
            int row = mBase + wm * 64 + mi * 16 + g;
            int col = nBase + wn * 32 + ni * 8 + tg * 2;
            if (col < N) {
                *(float2*)&C[(size_t)row * N + col] =
                    make_float2(acc[mi][ni][0], acc[mi][ni][1]);
                *(float2*)&C[(size_t)(row + 8) * N + col] =
                    make_float2(acc[mi][ni][2], acc[mi][ni][3]);
            }
        }
}

// ---------------- depthwise 3x3 conv + bias + SiLU ----------------
__global__ void conv_silu(const float* __restrict__ A1, const float* __restrict__ cw,
                          const float* __restrict__ cb, float* __restrict__ xc)
{
    int c = blockIdx.x * 256 + threadIdx.x;   // 0..1791
    int r = blockIdx.y;                        // 0..32767
    int pos = r & 1023;
    int y = pos >> 5, x = pos & 31;
    size_t base = (size_t)(r - pos) * NPROJ;   // start of this image's rows
    float s = cb[c];
#pragma unroll
    for (int dy = 0; dy < 3; dy++) {
        int yy = y + dy - 1;
        if ((unsigned)yy >= 32u) continue;
#pragma unroll
        for (int dx = 0; dx < 3; dx++) {
            int xx = x + dx - 1;
            if ((unsigned)xx >= 32u) continue;
            s += A1[base + (size_t)(yy * 32 + xx) * NPROJ + 1536 + c] * cw[c * 9 + dy * 3 + dx];
        }
    }
    xc[(size_t)r * CONVD + c] = s / (1.f + __expf(-s));
}

// ---------------- selective scan: one warp per (dir, b, h) ----------------
struct Fetch { float dt, B0, B1, C0, C1; float2 x; };

__global__ void __launch_bounds__(128)
scan_kernel(const float* __restrict__ A1, const float* __restrict__ xc,
            float* __restrict__ yall)
{
    __shared__ ulonglong2 sSC[4][64];
    const int lane = threadIdx.x & 31, ws = threadIdx.x >> 5;
    const int W = blockIdx.x * 4 + ws;             // 0..3071
    const int k = W / 768, rem = W % 768;
    const int b = rem / 24, h = rem % 24;
    const int g = k >> 1, rev = k & 1;
    const size_t rbase = (size_t)b * 1024;
    float* yout = yall + (size_t)k * ROWS * DINNER;

    ull hst[64];
#pragma unroll
    for (int n = 0; n < 64; n++) hst[n] = 0ull;

    Fetch cur, nxt;
    {
        int tt = rev ? 1023 : 0;
        size_t r = rbase + tt;
        const float* xr = &xc[r * CONVD];
        cur.dt = __ldg(&A1[r * NPROJ + 3328 + k * 24 + h]);
        cur.B0 = __ldg(&xr[1536 + g * 64 + lane]);
        cur.B1 = __ldg(&xr[1536 + g * 64 + lane + 32]);
        cur.C0 = __ldg(&xr[1664 + g * 64 + lane]);
        cur.C1 = __ldg(&xr[1664 + g * 64 + lane + 32]);
        cur.x  = *(const float2*)&xr[h * 64 + lane * 2];
    }

    for (int t = 0; t < 1024; t++) {
        if (t < 1023) {  // prefetch next step
            int tt = rev ? 1022 - t : t + 1;
            size_t r = rbase + tt;
            const float* xr = &xc[r * CONVD];
            nxt.dt = __ldg(&A1[r * NPROJ + 3328 + k * 24 + h]);
            nxt.B0 = __ldg(&xr[1536 + g * 64 + lane]);
            nxt.B1 = __ldg(&xr[1536 + g * 64 + lane + 32]);
            nxt.C0 = __ldg(&xr[1664 + g * 64 + lane]);
            nxt.C1 = __ldg(&xr[1664 + g * 64 + lane + 32]);
            nxt.x  = *(const float2*)&xr[h * 64 + lane * 2];
        }
        float dtp = cur.dt > 20.f ? cur.dt : log1pf(__expf(cur.dt));
        float a = __expf(-dtp);
        __syncwarp();
        sSC[ws][lane]      = make_ulonglong2(pack2(dtp * cur.B0), pack2(cur.C0));
        sSC[ws][lane + 32] = make_ulonglong2(pack2(dtp * cur.B1), pack2(cur.C1));
        __syncwarp();

        ull a2 = pack2(a);
        ull x2;
        asm("mov.b64 %0,{%1,%2};" : "=l"(x2)
            : "r"(__float_as_uint(cur.x.x)), "r"(__float_as_uint(cur.x.y)));
        ull y0 = 0ull, y1 = 0ull;
#pragma unroll
        for (int n = 0; n < 64; n += 2) {
            ulonglong2 s0 = sSC[ws][n];
            hst[n] = fma2(a2, hst[n], mul2(s0.x, x2));
            y0 = fma2(s0.y, hst[n], y0);
            ulonglong2 s1 = sSC[ws][n + 1];
            hst[n + 1] = fma2(a2, hst[n + 1], mul2(s1.x, x2));
            y1 = fma2(s1.y, hst[n + 1], y1);
        }
        ull ys = add2(y0, y1);
        uint32_t lo, hi;
        asm("mov.b64 {%0,%1},%2;" : "=r"(lo), "=r"(hi) : "l"(ys));
        int tt = rev ? 1023 - t : t;
        *(float2*)&yout[(rbase + tt) * DINNER + h * 64 + lane * 2] =
            make_float2(__uint_as_float(lo), __uint_as_float(hi));
        if (t < 1023) cur = nxt;
    }
}

// ---------------- sum 4 dirs + gate (silu(z)) + RMSNorm -> bf16 split ----------------
__global__ void __launch_bounds__(256)
gate_rms(const float* __restrict__ A1, const float* __restrict__ yall,
         const float* __restrict__ nw,
         __nv_bfloat16* __restrict__ Yh, __nv_bfloat16* __restrict__ Yl)
{
    __shared__ float red[8];
    __shared__ float s_scale;
    const int r = blockIdx.x, tid = threadIdx.x;
    const float* y0 = yall + (size_t)r * DINNER;
    const float* y1 = y0 + (size_t)ROWS * DINNER;
    const float* y2 = y1 + (size_t)ROWS * DINNER;
    const float* y3 = y2 + (size_t)ROWS * DINNER;

    float v[6]; float ss = 0.f;
#pragma unroll
    for (int i = 0; i < 6; i++) {
        int d = tid + i * 256;
        float y = y0[d] + y1[d] + y2[d] + y3[d];
        float z = A1[(size_t)r * NPROJ + d];
        float zs = z / (1.f + __expf(-z));
        v[i] = y * zs;
        ss += v[i] * v[i];
    }
#pragma unroll
    for (int o = 16; o; o >>= 1) ss += __shfl_xor_sync(0xffffffffu, ss, o);
    if ((tid & 31) == 0) red[tid >> 5] = ss;
    __syncthreads();
    if (tid == 0) {
        float t = 0.f;
#pragma unroll
        for (int i = 0; i < 8; i++) t += red[i];
        s_scale = rsqrtf(t / 1536.f + 1e-5f);
    }
    __syncthreads();
    float scale = s_scale;
#pragma unroll
    for (int i = 0; i < 6; i++) {
        int d = tid + i * 256;
        float yn = v[i] * scale * nw[d];
        __nv_bfloat16 hv = __float2bfloat16(yn);
        size_t idx = (size_t)r * DINNER + d;
        Yh[idx] = hv;
        Yl[idx] = __float2bfloat16(yn - __bfloat162float(hv));
    }
}

// ---------------- host launcher ----------------
extern "C" void kernel_launch(void* const* d_in, const int* in_sizes, int n_in,
                              void* d_out, int out_size)
{
    const float* u      = (const float*)d_in[0];
    const float* w_in   = (const float*)d_in[1];
    const float* conv_w = (const float*)d_in[2];
    const float* conv_b = (const float*)d_in[3];
    const float* norm_w = (const float*)d_in[4];
    const float* w_out  = (const float*)d_in[5];

    void *pA1, *pxc, *py, *pUh, *pUl, *pWih, *pWil, *pWoh, *pWol, *pYh, *pYl;
    cudaGetSymbolAddress(&pA1, g_A1);
    cudaGetSymbolAddress(&pxc, g_xc);
    cudaGetSymbolAddress(&py,  g_y);
    cudaGetSymbolAddress(&pUh, g_Uh);   cudaGetSymbolAddress(&pUl, g_Ul);
    cudaGetSymbolAddress(&pWih, g_Wih); cudaGetSymbolAddress(&pWil, g_Wil);
    cudaGetSymbolAddress(&pWoh, g_Woh); cudaGetSymbolAddress(&pWol, g_Wol);
    cudaGetSymbolAddress(&pYh, g_Yh);   cudaGetSymbolAddress(&pYl, g_Yl);

    size_t nu  = (size_t)ROWS * DMODEL;
    size_t nwi = (size_t)NPROJ * DMODEL;
    size_t nwo = (size_t)DMODEL * DINNER;
    cvt_kernel<<<(unsigned)((nu  + 255) / 256), 256>>>(u,     (__nv_bfloat16*)pUh,  (__nv_bfloat16*)pUl,  nu);
    cvt_kernel<<<(unsigned)((nwi + 255) / 256), 256>>>(w_in,  (__nv_bfloat16*)pWih, (__nv_bfloat16*)pWil, nwi);
    cvt_kernel<<<(unsigned)((nwo + 255) / 256), 256>>>(w_out, (__nv_bfloat16*)pWoh, (__nv_bfloat16*)pWol, nwo);

    // in-projection: (32768 x 3424) = u (32768 x 768) @ w_in^T
    gemm_bf16x3<<<dim3(27, 256), 256>>>((__nv_bfloat16*)pUh, (__nv_bfloat16*)pUl,
                                        (__nv_bfloat16*)pWih, (__nv_bfloat16*)pWil,
                                        (float*)pA1, ROWS, NPROJ, DMODEL);

    conv_silu<<<dim3(7, ROWS), 256>>>((const float*)pA1, conv_w, conv_b, (float*)pxc);

    scan_kernel<<<768, 128>>>((const float*)pA1, (const float*)pxc, (float*)py);

    gate_rms<<<ROWS, 256>>>((const float*)pA1, (const float*)py, norm_w,
                            (__nv_bfloat16*)pYh, (__nv_bfloat16*)pYl);

    // out-projection: (32768 x 768) = yn (32768 x 1536) @ w_out^T
    gemm_bf16x3<<<dim3(6, 256), 256>>>((__nv_bfloat16*)pYh, (__nv_bfloat16*)pYl,
                                       (__nv_bfloat16*)pWoh, (__nv_bfloat16*)pWol,
                                       (float*)d_out, ROWS, DMODEL, DINNER);
}

// round 6
// speedup vs baseline: 1.0859x; 1.0859x over previous
#include <cuda_runtime.h>
#include <cuda_bf16.h>
#include <cstdint>
#include <cstddef>

#define ROWS   32768
#define NPROJ  3424
#define CONVD  1792
#define DINNER 1536
#define DMODEL 768

typedef unsigned long long ull;

// ---------------- scratch (device globals; no runtime allocation) ----------------
__device__ float g_A1[(size_t)ROWS * NPROJ];            // zxBCdt
__device__ float g_xc[(size_t)ROWS * CONVD];            // conv+silu output
__device__ float g_y [(size_t)4 * ROWS * DINNER];       // per-direction scan outputs
__device__ __nv_bfloat16 g_Uh [(size_t)ROWS * DMODEL];
__device__ __nv_bfloat16 g_Ul [(size_t)ROWS * DMODEL];
__device__ __nv_bfloat16 g_Wih[(size_t)NPROJ * DMODEL];
__device__ __nv_bfloat16 g_Wil[(size_t)NPROJ * DMODEL];
__device__ __nv_bfloat16 g_Woh[(size_t)DMODEL * DINNER];
__device__ __nv_bfloat16 g_Wol[(size_t)DMODEL * DINNER];
__device__ __nv_bfloat16 g_Yh [(size_t)ROWS * DINNER];
__device__ __nv_bfloat16 g_Yl [(size_t)ROWS * DINNER];

// ---------------- packed f32x2 helpers ----------------
__device__ __forceinline__ ull fma2(ull a, ull b, ull c) {
    ull d; asm("fma.rn.f32x2 %0,%1,%2,%3;" : "=l"(d) : "l"(a), "l"(b), "l"(c)); return d;
}
__device__ __forceinline__ ull mul2(ull a, ull b) {
    ull d; asm("mul.rn.f32x2 %0,%1,%2;" : "=l"(d) : "l"(a), "l"(b)); return d;
}
__device__ __forceinline__ ull add2(ull a, ull b) {
    ull d; asm("add.rn.f32x2 %0,%1,%2;" : "=l"(d) : "l"(a), "l"(b)); return d;
}
__device__ __forceinline__ ull pack2(float x) {
    unsigned r = __float_as_uint(x);
    ull d; asm("mov.b64 %0,{%1,%1};" : "=l"(d) : "r"(r)); return d;
}

// ---------------- fp32 -> bf16 hi/lo split ----------------
__global__ void cvt_kernel(const float* __restrict__ s,
                           __nv_bfloat16* __restrict__ hi,
                           __nv_bfloat16* __restrict__ lo, size_t n) {
    size_t i = (size_t)blockIdx.x * blockDim.x + threadIdx.x;
    if (i >= n) return;
    float v = s[i];
    __nv_bfloat16 h = __float2bfloat16(v);
    hi[i] = h;
    lo[i] = __float2bfloat16(v - __bfloat162float(h));
}

// =========== tensor-core GEMM (mma.sync): C[M,N] = A[M,K] * B[N,K]^T ===========
// 128x128 CTA tile, KC=32 chunks, 3-stage cp.async pipeline, 3-pass bf16 split.

#define SK 40                 // smem row stride in halves (32 + 8 pad)
#define AR_BYTES (128 * SK * 2)          // 10240 per array
#define STG_BYTES (4 * AR_BYTES)         // 40960 per stage (Ah|Al|Bh|Bl)
#define GEMM_SMEM (3 * STG_BYTES)        // 122880

__device__ __forceinline__ void mma_bf16(float* c, const uint32_t* a, const uint32_t* b) {
    asm volatile("mma.sync.aligned.m16n8k16.row.col.f32.bf16.bf16.f32 "
                 "{%0,%1,%2,%3},{%4,%5,%6,%7},{%8,%9},{%0,%1,%2,%3};"
                 : "+f"(c[0]), "+f"(c[1]), "+f"(c[2]), "+f"(c[3])
                 : "r"(a[0]), "r"(a[1]), "r"(a[2]), "r"(a[3]), "r"(b[0]), "r"(b[1]));
}
__device__ __forceinline__ void ldsm4(uint32_t* r, const __nv_bfloat16* p) {
    uint32_t a = (uint32_t)__cvta_generic_to_shared(p);
    asm volatile("ldmatrix.sync.aligned.m8n8.x4.shared.b16 {%0,%1,%2,%3},[%4];"
                 : "=r"(r[0]), "=r"(r[1]), "=r"(r[2]), "=r"(r[3]) : "r"(a));
}
__device__ __forceinline__ void ldsm2(uint32_t* r, const __nv_bfloat16* p) {
    uint32_t a = (uint32_t)__cvta_generic_to_shared(p);
    asm volatile("ldmatrix.sync.aligned.m8n8.x2.shared.b16 {%0,%1},[%2];"
                 : "=r"(r[0]), "=r"(r[1]) : "r"(a));
}
__device__ __forceinline__ void cpa16(uint32_t dst, const void* src, int sz) {
    asm volatile("cp.async.cg.shared.global [%0], [%1], 16, %2;"
                 :: "r"(dst), "l"(src), "r"(sz));
}

// load one KC=32 chunk into stage s.  256 threads, 2 chunk-slots per array each.
__device__ __forceinline__ void load_stage(uint32_t sbase,
        const __nv_bfloat16* __restrict__ Ah, const __nv_bfloat16* __restrict__ Al,
        const __nv_bfloat16* __restrict__ Bh, const __nv_bfloat16* __restrict__ Bl,
        int mBase, int nBase, int N, int K, int k0, int tid)
{
#pragma unroll
    for (int i = 0; i < 2; i++) {
        int idx = tid + i * 256;          // 0..511
        int row = idx >> 2, seg = idx & 3;
        uint32_t so = (uint32_t)(row * (SK * 2) + seg * 16);
        size_t aoff = (size_t)(mBase + row) * K + k0 + seg * 8;
        cpa16(sbase + so,                Ah + aoff, 16);
        cpa16(sbase + AR_BYTES + so,     Al + aoff, 16);
        int brow = nBase + row;
        int ok = (brow < N) ? 16 : 0;
        size_t boff = (size_t)(ok ? brow : 0) * K + k0 + seg * 8;
        cpa16(sbase + 2 * AR_BYTES + so, Bh + boff, ok);
        cpa16(sbase + 3 * AR_BYTES + so, Bl + boff, ok);
    }
    asm volatile("cp.async.commit_group;");
}

__global__ void __launch_bounds__(256)
gemm_bf16x3(const __nv_bfloat16* __restrict__ Ah, const __nv_bfloat16* __restrict__ Al,
            const __nv_bfloat16* __restrict__ Bh, const __nv_bfloat16* __restrict__ Bl,
            float* __restrict__ C, int M, int N, int K)
{
    extern __shared__ char smem[];
    uint32_t sb = (uint32_t)__cvta_generic_to_shared(smem);
    const int tid = threadIdx.x, lane = tid & 31, warp = tid >> 5;
    const int wm = warp >> 2, wn = warp & 3;       // 2x4 warp grid; warp tile 64m x 32n
    const int g = lane >> 2, tg = lane & 3;
    const int mBase = blockIdx.y * 128, nBase = blockIdx.x * 128;

    float acc[4][4][4];
#pragma unroll
    for (int mi = 0; mi < 4; mi++)
#pragma unroll
        for (int ni = 0; ni < 4; ni++)
#pragma unroll
            for (int q = 0; q < 4; q++) acc[mi][ni][q] = 0.f;

    const int KT = K / 32;

    // prologue: stages 0 and 1 in flight
    load_stage(sb,             Ah, Al, Bh, Bl, mBase, nBase, N, K, 0,  tid);
    load_stage(sb + STG_BYTES, Ah, Al, Bh, Bl, mBase, nBase, N, K, 32, tid);

    for (int kt = 0; kt < KT; kt++) {
        const int s = kt % 3;
        if (kt + 1 < KT) asm volatile("cp.async.wait_group 1;" ::: "memory");
        else             asm volatile("cp.async.wait_group 0;" ::: "memory");
        __syncthreads();

        // issue loads for chunk kt+2 into the stage computed last iteration
        if (kt + 2 < KT) {
            load_stage(sb + ((kt + 2) % 3) * STG_BYTES,
                       Ah, Al, Bh, Bl, mBase, nBase, N, K, (kt + 2) * 32, tid);
        }

        const __nv_bfloat16* sAh = (const __nv_bfloat16*)(smem + s * STG_BYTES);
        const __nv_bfloat16* sAl = (const __nv_bfloat16*)(smem + s * STG_BYTES + AR_BYTES);
        const __nv_bfloat16* sBh = (const __nv_bfloat16*)(smem + s * STG_BYTES + 2 * AR_BYTES);
        const __nv_bfloat16* sBl = (const __nv_bfloat16*)(smem + s * STG_BYTES + 3 * AR_BYTES);

#pragma unroll
        for (int kk = 0; kk < 32; kk += 16) {
            uint32_t aH[4][4], aL[4][4], bH[4][2], bL[4][2];
#pragma unroll
            for (int mi = 0; mi < 4; mi++) {
                int off = (wm * 64 + mi * 16 + (lane & 15)) * SK + kk + ((lane >> 4) << 3);
                ldsm4(aH[mi], &sAh[off]);
                ldsm4(aL[mi], &sAl[off]);
            }
#pragma unroll
            for (int ni = 0; ni < 4; ni++) {
                int off = (wn * 32 + ni * 8 + (lane & 7)) * SK + kk + (((lane >> 3) & 1) << 3);
                ldsm2(bH[ni], &sBh[off]);
                ldsm2(bL[ni], &sBl[off]);
            }
#pragma unroll
            for (int mi = 0; mi < 4; mi++)
#pragma unroll
                for (int ni = 0; ni < 4; ni++) {
                    mma_bf16(acc[mi][ni], aH[mi], bH[ni]);
                    mma_bf16(acc[mi][ni], aL[mi], bH[ni]);
                    mma_bf16(acc[mi][ni], aH[mi], bL[ni]);
                }
        }
        __syncthreads();
    }

    // ---- epilogue ----
#pragma unroll
    for (int mi = 0; mi < 4; mi++)
#pragma unroll
        for (int ni = 0; ni < 4; ni++) {
            int row = mBase + wm * 64 + mi * 16 + g;
            int col = nBase + wn * 32 + ni * 8 + tg * 2;
            if (col < N) {
                *(float2*)&C[(size_t)row * N + col] =
                    make_float2(acc[mi][ni][0], acc[mi][ni][1]);
                *(float2*)&C[(size_t)(row + 8) * N + col] =
                    make_float2(acc[mi][ni][2], acc[mi][ni][3]);
            }
        }
}

// ---------------- depthwise 3x3 conv + bias + SiLU ----------------
__global__ void conv_silu(const float* __restrict__ A1, const float* __restrict__ cw,
                          const float* __restrict__ cb, float* __restrict__ xc)
{
    int c = blockIdx.x * 256 + threadIdx.x;   // 0..1791
    int r = blockIdx.y;                        // 0..32767
    int pos = r & 1023;
    int y = pos >> 5, x = pos & 31;
    size_t base = (size_t)(r - pos) * NPROJ;
    float s = cb[c];
#pragma unroll
    for (int dy = 0; dy < 3; dy++) {
        int yy = y + dy - 1;
        if ((unsigned)yy >= 32u) continue;
#pragma unroll
        for (int dx = 0; dx < 3; dx++) {
            int xx = x + dx - 1;
            if ((unsigned)xx >= 32u) continue;
            s += A1[base + (size_t)(yy * 32 + xx) * NPROJ + 1536 + c] * cw[c * 9 + dy * 3 + dx];
        }
    }
    xc[(size_t)r * CONVD + c] = s / (1.f + __expf(-s));
}

// ---------------- selective scan: one warp per (dir, b, h) ----------------
struct Fetch { float dt, B0, B1, C0, C1; float2 x; };

__global__ void __launch_bounds__(128)
scan_kernel(const float* __restrict__ A1, const float* __restrict__ xc,
            float* __restrict__ yall)
{
    __shared__ ulonglong2 sSC[4][64];
    const int lane = threadIdx.x & 31, ws = threadIdx.x >> 5;
    const int W = blockIdx.x * 4 + ws;             // 0..3071
    const int k = W / 768, rem = W % 768;
    const int b = rem / 24, h = rem % 24;
    const int g = k >> 1, rev = k & 1;
    const size_t rbase = (size_t)b * 1024;
    float* yout = yall + (size_t)k * ROWS * DINNER;

    ull hst[64];
#pragma unroll
    for (int n = 0; n < 64; n++) hst[n] = 0ull;

    Fetch cur, nxt;
    {
        int tt = rev ? 1023 : 0;
        size_t r = rbase + tt;
        const float* xr = &xc[r * CONVD];
        cur.dt = __ldg(&A1[r * NPROJ + 3328 + k * 24 + h]);
        cur.B0 = __ldg(&xr[1536 + g * 64 + lane]);
        cur.B1 = __ldg(&xr[1536 + g * 64 + lane + 32]);
        cur.C0 = __ldg(&xr[1664 + g * 64 + lane]);
        cur.C1 = __ldg(&xr[1664 + g * 64 + lane + 32]);
        cur.x  = *(const float2*)&xr[h * 64 + lane * 2];
    }

    for (int t = 0; t < 1024; t++) {
        if (t < 1023) {
            int tt = rev ? 1022 - t : t + 1;
            size_t r = rbase + tt;
            const float* xr = &xc[r * CONVD];
            nxt.dt = __ldg(&A1[r * NPROJ + 3328 + k * 24 + h]);
            nxt.B0 = __ldg(&xr[1536 + g * 64 + lane]);
            nxt.B1 = __ldg(&xr[1536 + g * 64 + lane + 32]);
            nxt.C0 = __ldg(&xr[1664 + g * 64 + lane]);
            nxt.C1 = __ldg(&xr[1664 + g * 64 + lane + 32]);
            nxt.x  = *(const float2*)&xr[h * 64 + lane * 2];
        }
        float dtp = cur.dt > 20.f ? cur.dt : log1pf(__expf(cur.dt));
        float a = __expf(-dtp);
        __syncwarp();
        sSC[ws][lane]      = make_ulonglong2(pack2(dtp * cur.B0), pack2(cur.C0));
        sSC[ws][lane + 32] = make_ulonglong2(pack2(dtp * cur.B1), pack2(cur.C1));
        __syncwarp();

        ull a2 = pack2(a);
        ull x2;
        asm("mov.b64 %0,{%1,%2};" : "=l"(x2)
            : "r"(__float_as_uint(cur.x.x)), "r"(__float_as_uint(cur.x.y)));
        ull y0 = 0ull, y1 = 0ull;
#pragma unroll
        for (int n = 0; n < 64; n += 2) {
            ulonglong2 s0 = sSC[ws][n];
            hst[n] = fma2(a2, hst[n], mul2(s0.x, x2));
            y0 = fma2(s0.y, hst[n], y0);
            ulonglong2 s1 = sSC[ws][n + 1];
            hst[n + 1] = fma2(a2, hst[n + 1], mul2(s1.x, x2));
            y1 = fma2(s1.y, hst[n + 1], y1);
        }
        ull ys = add2(y0, y1);
        uint32_t lo, hi;
        asm("mov.b64 {%0,%1},%2;" : "=r"(lo), "=r"(hi) : "l"(ys));
        int tt = rev ? 1023 - t : t;
        *(float2*)&yout[(rbase + tt) * DINNER + h * 64 + lane * 2] =
            make_float2(__uint_as_float(lo), __uint_as_float(hi));
        if (t < 1023) cur = nxt;
    }
}

// ---------------- sum 4 dirs + gate (silu(z)) + RMSNorm -> bf16 split ----------------
__global__ void __launch_bounds__(256)
gate_rms(const float* __restrict__ A1, const float* __restrict__ yall,
         const float* __restrict__ nw,
         __nv_bfloat16* __restrict__ Yh, __nv_bfloat16* __restrict__ Yl)
{
    __shared__ float red[8];
    __shared__ float s_scale;
    const int r = blockIdx.x, tid = threadIdx.x;
    const float* y0 = yall + (size_t)r * DINNER;
    const float* y1 = y0 + (size_t)ROWS * DINNER;
    const float* y2 = y1 + (size_t)ROWS * DINNER;
    const float* y3 = y2 + (size_t)ROWS * DINNER;

    float v[6]; float ss = 0.f;
#pragma unroll
    for (int i = 0; i < 6; i++) {
        int d = tid + i * 256;
        float y = y0[d] + y1[d] + y2[d] + y3[d];
        float z = A1[(size_t)r * NPROJ + d];
        float zs = z / (1.f + __expf(-z));
        v[i] = y * zs;
        ss += v[i] * v[i];
    }
#pragma unroll
    for (int o = 16; o; o >>= 1) ss += __shfl_xor_sync(0xffffffffu, ss, o);
    if ((tid & 31) == 0) red[tid >> 5] = ss;
    __syncthreads();
    if (tid == 0) {
        float t = 0.f;
#pragma unroll
        for (int i = 0; i < 8; i++) t += red[i];
        s_scale = rsqrtf(t / 1536.f + 1e-5f);
    }
    __syncthreads();
    float scale = s_scale;
#pragma unroll
    for (int i = 0; i < 6; i++) {
        int d = tid + i * 256;
        float yn = v[i] * scale * nw[d];
        __nv_bfloat16 hv = __float2bfloat16(yn);
        size_t idx = (size_t)r * DINNER + d;
        Yh[idx] = hv;
        Yl[idx] = __float2bfloat16(yn - __bfloat162float(hv));
    }
}

// ---------------- host launcher ----------------
extern "C" void kernel_launch(void* const* d_in, const int* in_sizes, int n_in,
                              void* d_out, int out_size)
{
    const float* u      = (const float*)d_in[0];
    const float* w_in   = (const float*)d_in[1];
    const float* conv_w = (const float*)d_in[2];
    const float* conv_b = (const float*)d_in[3];
    const float* norm_w = (const float*)d_in[4];
    const float* w_out  = (const float*)d_in[5];

    void *pA1, *pxc, *py, *pUh, *pUl, *pWih, *pWil, *pWoh, *pWol, *pYh, *pYl;
    cudaGetSymbolAddress(&pA1, g_A1);
    cudaGetSymbolAddress(&pxc, g_xc);
    cudaGetSymbolAddress(&py,  g_y);
    cudaGetSymbolAddress(&pUh, g_Uh);   cudaGetSymbolAddress(&pUl, g_Ul);
    cudaGetSymbolAddress(&pWih, g_Wih); cudaGetSymbolAddress(&pWil, g_Wil);
    cudaGetSymbolAddress(&pWoh, g_Woh); cudaGetSymbolAddress(&pWol, g_Wol);
    cudaGetSymbolAddress(&pYh, g_Yh);   cudaGetSymbolAddress(&pYl, g_Yl);

    cudaFuncSetAttribute(gemm_bf16x3, cudaFuncAttributeMaxDynamicSharedMemorySize, GEMM_SMEM);

    size_t nu  = (size_t)ROWS * DMODEL;
    size_t nwi = (size_t)NPROJ * DMODEL;
    size_t nwo = (size_t)DMODEL * DINNER;
    cvt_kernel<<<(unsigned)((nu  + 255) / 256), 256>>>(u,     (__nv_bfloat16*)pUh,  (__nv_bfloat16*)pUl,  nu);
    cvt_kernel<<<(unsigned)((nwi + 255) / 256), 256>>>(w_in,  (__nv_bfloat16*)pWih, (__nv_bfloat16*)pWil, nwi);
    cvt_kernel<<<(unsigned)((nwo + 255) / 256), 256>>>(w_out, (__nv_bfloat16*)pWoh, (__nv_bfloat16*)pWol, nwo);

    // in-projection: (32768 x 3424) = u (32768 x 768) @ w_in^T
    gemm_bf16x3<<<dim3(27, 256), 256, GEMM_SMEM>>>(
        (__nv_bfloat16*)pUh, (__nv_bfloat16*)pUl,
        (__nv_bfloat16*)pWih, (__nv_bfloat16*)pWil,
        (float*)pA1, ROWS, NPROJ, DMODEL);

    conv_silu<<<dim3(7, ROWS), 256>>>((const float*)pA1, conv_w, conv_b, (float*)pxc);

    scan_kernel<<<768, 128>>>((const float*)pA1, (const float*)pxc, (float*)py);

    gate_rms<<<ROWS, 256>>>((const float*)pA1, (const float*)py, norm_w,
                            (__nv_bfloat16*)pYh, (__nv_bfloat16*)pYl);

    // out-projection: (32768 x 768) = yn (32768 x 1536) @ w_out^T
    gemm_bf16x3<<<dim3(6, 256), 256, GEMM_SMEM>>>(
        (__nv_bfloat16*)pYh, (__nv_bfloat16*)pYl,
        (__nv_bfloat16*)pWoh, (__nv_bfloat16*)pWol,
        (float*)d_out, ROWS, DMODEL, DINNER);
}

// round 8
// speedup vs baseline: 1.1680x; 1.0756x over previous
#include <cuda_runtime.h>
#include <cuda_bf16.h>
#include <cstdint>
#include <cstddef>

#define ROWS   32768
#define NPROJ  3424
#define CONVD  1792
#define DINNER 1536
#define DMODEL 768

typedef unsigned long long ull;

// ---------------- scratch (device globals; no runtime allocation) ----------------
__device__ float g_A1[(size_t)ROWS * NPROJ];            // zxBCdt
__device__ float g_xc[(size_t)ROWS * CONVD];            // conv+silu output
__device__ float g_y [(size_t)4 * ROWS * DINNER];       // per-direction scan outputs
__device__ __nv_bfloat16 g_Uh [(size_t)ROWS * DMODEL];
__device__ __nv_bfloat16 g_Ul [(size_t)ROWS * DMODEL];
__device__ __nv_bfloat16 g_Wih[(size_t)NPROJ * DMODEL];
__device__ __nv_bfloat16 g_Wil[(size_t)NPROJ * DMODEL];
__device__ __nv_bfloat16 g_Woh[(size_t)DMODEL * DINNER];
__device__ __nv_bfloat16 g_Wol[(size_t)DMODEL * DINNER];
__device__ __nv_bfloat16 g_Yh [(size_t)ROWS * DINNER];
__device__ __nv_bfloat16 g_Yl [(size_t)ROWS * DINNER];

// ---------------- packed f32x2 helpers ----------------
__device__ __forceinline__ ull fma2(ull a, ull b, ull c) {
    ull d; asm("fma.rn.f32x2 %0,%1,%2,%3;" : "=l"(d) : "l"(a), "l"(b), "l"(c)); return d;
}
__device__ __forceinline__ ull mul2(ull a, ull b) {
    ull d; asm("mul.rn.f32x2 %0,%1,%2;" : "=l"(d) : "l"(a), "l"(b)); return d;
}
__device__ __forceinline__ ull add2(ull a, ull b) {
    ull d; asm("add.rn.f32x2 %0,%1,%2;" : "=l"(d) : "l"(a), "l"(b)); return d;
}
__device__ __forceinline__ ull pack2(float x) {
    unsigned r = __float_as_uint(x);
    ull d; asm("mov.b64 %0,{%1,%1};" : "=l"(d) : "r"(r)); return d;
}

// ---------------- fp32 -> bf16 hi/lo split ----------------
__global__ void cvt_kernel(const float* __restrict__ s,
                           __nv_bfloat16* __restrict__ hi,
                           __nv_bfloat16* __restrict__ lo, size_t n) {
    size_t i = (size_t)blockIdx.x * blockDim.x + threadIdx.x;
    if (i >= n) return;
    float v = s[i];
    __nv_bfloat16 h = __float2bfloat16(v);
    hi[i] = h;
    lo[i] = __float2bfloat16(v - __bfloat162float(h));
}

// =========== tensor-core GEMM (mma.sync): C[M,N] = A[M,K] * B[N,K]^T ===========
// 128x128 CTA tile, KC=32 chunks, 2-stage double buffer, 2 CTAs/SM,
// 3-pass bf16 split (AhBh + AlBh + AhBl), fp32 accumulate.

#define SK 40                            // smem row stride in halves (32 + 8 pad)
#define AR_BYTES (128 * SK * 2)          // 10240 per array
#define STG_BYTES (4 * AR_BYTES)         // 40960 per stage (Ah|Al|Bh|Bl)
#define GEMM_SMEM (2 * STG_BYTES)        // 81920

__device__ __forceinline__ void mma_bf16(float* c, const uint32_t* a, const uint32_t* b) {
    asm volatile("mma.sync.aligned.m16n8k16.row.col.f32.bf16.bf16.f32 "
                 "{%0,%1,%2,%3},{%4,%5,%6,%7},{%8,%9},{%0,%1,%2,%3};"
                 : "+f"(c[0]), "+f"(c[1]), "+f"(c[2]), "+f"(c[3])
                 : "r"(a[0]), "r"(a[1]), "r"(a[2]), "r"(a[3]), "r"(b[0]), "r"(b[1]));
}
__device__ __forceinline__ void ldsm4(uint32_t* r, const __nv_bfloat16* p) {
    uint32_t a = (uint32_t)__cvta_generic_to_shared(p);
    asm volatile("ldmatrix.sync.aligned.m8n8.x4.shared.b16 {%0,%1,%2,%3},[%4];"
                 : "=r"(r[0]), "=r"(r[1]), "=r"(r[2]), "=r"(r[3]) : "r"(a));
}
__device__ __forceinline__ void ldsm2(uint32_t* r, const __nv_bfloat16* p) {
    uint32_t a = (uint32_t)__cvta_generic_to_shared(p);
    asm volatile("ldmatrix.sync.aligned.m8n8.x2.shared.b16 {%0,%1},[%2];"
                 : "=r"(r[0]), "=r"(r[1]) : "r"(a));
}
__device__ __forceinline__ void cpa16(uint32_t dst, const void* src, int sz) {
    asm volatile("cp.async.cg.shared.global [%0], [%1], 16, %2;"
                 :: "r"(dst), "l"(src), "r"(sz));
}

// load one KC=32 chunk into a stage.  256 threads, 2 slots per array each.
__device__ __forceinline__ void load_stage(uint32_t sbase,
        const __nv_bfloat16* __restrict__ Ah, const __nv_bfloat16* __restrict__ Al,
        const __nv_bfloat16* __restrict__ Bh, const __nv_bfloat16* __restrict__ Bl,
        int mBase, int nBase, int N, int K, int k0, int tid)
{
#pragma unroll
    for (int i = 0; i < 2; i++) {
        int idx = tid + i * 256;          // 0..511
        int row = idx >> 2, seg = idx & 3;
        uint32_t so = (uint32_t)(row * (SK * 2) + seg * 16);
        size_t aoff = (size_t)(mBase + row) * K + k0 + seg * 8;
        cpa16(sbase + so,                Ah + aoff, 16);
        cpa16(sbase + AR_BYTES + so,     Al + aoff, 16);
        int brow = nBase + row;
        int ok = (brow < N) ? 16 : 0;
        size_t boff = (size_t)(ok ? brow : 0) * K + k0 + seg * 8;
        cpa16(sbase + 2 * AR_BYTES + so, Bh + boff, ok);
        cpa16(sbase + 3 * AR_BYTES + so, Bl + boff, ok);
    }
    asm volatile("cp.async.commit_group;");
}

__global__ void __launch_bounds__(256, 2)
gemm_bf16x3(const __nv_bfloat16* __restrict__ Ah, const __nv_bfloat16* __restrict__ Al,
            const __nv_bfloat16* __restrict__ Bh, const __nv_bfloat16* __restrict__ Bl,
            float* __restrict__ C, int M, int N, int K)
{
    extern __shared__ char smem[];
    uint32_t sb = (uint32_t)__cvta_generic_to_shared(smem);
    const int tid = threadIdx.x, lane = tid & 31, warp = tid >> 5;
    const int wm = warp >> 2, wn = warp & 3;       // 2x4 warp grid; warp tile 64m x 32n
    const int g = lane >> 2, tg = lane & 3;
    const int mBase = blockIdx.y * 128, nBase = blockIdx.x * 128;

    float acc[4][4][4];
#pragma unroll
    for (int mi = 0; mi < 4; mi++)
#pragma unroll
        for (int ni = 0; ni < 4; ni++)
#pragma unroll
            for (int q = 0; q < 4; q++) acc[mi][ni][q] = 0.f;

    const int KT = K / 32;

    // prologue: both stages in flight
    load_stage(sb,             Ah, Al, Bh, Bl, mBase, nBase, N, K, 0,  tid);
    load_stage(sb + STG_BYTES, Ah, Al, Bh, Bl, mBase, nBase, N, K, 32, tid);

    for (int kt = 0; kt < KT; kt++) {
        const int s = kt & 1;
        if (kt + 1 < KT) asm volatile("cp.async.wait_group 1;" ::: "memory");
        else             asm volatile("cp.async.wait_group 0;" ::: "memory");
        __syncthreads();

        const __nv_bfloat16* sAh = (const __nv_bfloat16*)(smem + s * STG_BYTES);
        const __nv_bfloat16* sAl = (const __nv_bfloat16*)(smem + s * STG_BYTES + AR_BYTES);
        const __nv_bfloat16* sBh = (const __nv_bfloat16*)(smem + s * STG_BYTES + 2 * AR_BYTES);
        const __nv_bfloat16* sBl = (const __nv_bfloat16*)(smem + s * STG_BYTES + 3 * AR_BYTES);

#pragma unroll
        for (int kk = 0; kk < 32; kk += 16) {
            uint32_t aH[4][4], bX[4][2];
            // pass 1: Ah * Bh
#pragma unroll
            for (int mi = 0; mi < 4; mi++) {
                int off = (wm * 64 + mi * 16 + (lane & 15)) * SK + kk + ((lane >> 4) << 3);
                ldsm4(aH[mi], &sAh[off]);
            }
#pragma unroll
            for (int ni = 0; ni < 4; ni++) {
                int off = (wn * 32 + ni * 8 + (lane & 7)) * SK + kk + (((lane >> 3) & 1) << 3);
                ldsm2(bX[ni], &sBh[off]);
            }
#pragma unroll
            for (int mi = 0; mi < 4; mi++)
#pragma unroll
                for (int ni = 0; ni < 4; ni++) mma_bf16(acc[mi][ni], aH[mi], bX[ni]);

            // pass 2: Al * Bh (reuse bX = Bh)
            {
                uint32_t aL[4][4];
#pragma unroll
                for (int mi = 0; mi < 4; mi++) {
                    int off = (wm * 64 + mi * 16 + (lane & 15)) * SK + kk + ((lane >> 4) << 3);
                    ldsm4(aL[mi], &sAl[off]);
                }
#pragma unroll
                for (int mi = 0; mi < 4; mi++)
#pragma unroll
                    for (int ni = 0; ni < 4; ni++) mma_bf16(acc[mi][ni], aL[mi], bX[ni]);
            }

            // pass 3: Ah * Bl (reuse bX regs for Bl)
#pragma unroll
            for (int ni = 0; ni < 4; ni++) {
                int off = (wn * 32 + ni * 8 + (lane & 7)) * SK + kk + (((lane >> 3) & 1) << 3);
                ldsm2(bX[ni], &sBl[off]);
            }
#pragma unroll
            for (int mi = 0; mi < 4; mi++)
#pragma unroll
                for (int ni = 0; ni < 4; ni++) mma_bf16(acc[mi][ni], aH[mi], bX[ni]);
        }
        __syncthreads();

        if (kt + 2 < KT) {
            load_stage(sb + s * STG_BYTES,
                       Ah, Al, Bh, Bl, mBase, nBase, N, K, (kt + 2) * 32, tid);
        }
    }

    // ---- epilogue ----
#pragma unroll
    for (int mi = 0; mi < 4; mi++)
#pragma unroll
        for (int ni = 0; ni < 4; ni++) {
            int row = mBase + wm * 64 + mi * 16 + g;
            int col = nBase + wn * 32 + ni * 8 + tg * 2;
            if (col < N) {
                *(float2*)&C[(size_t)row * N + col] =
                    make_float2(acc[mi][ni][0], acc[mi][ni][1]);
                *(float2*)&C[(size_t)(row + 8) * N + col] =
                    make_float2(acc[mi][ni][2], acc[mi][ni][3]);
            }
        }
}

// ---------------- depthwise 3x3 conv + bias + SiLU ----------------
__global__ void conv_silu(const float* __restrict__ A1, const float* __restrict__ cw,
                          const float* __restrict__ cb, float* __restrict__ xc)
{
    int c = blockIdx.x * 256 + threadIdx.x;   // 0..1791
    int r = blockIdx.y;                        // 0..32767
    int pos = r & 1023;
    int y = pos >> 5, x = pos & 31;
    size_t base = (size_t)(r - pos) * NPROJ;
    float s = cb[c];
#pragma unroll
    for (int dy = 0; dy < 3; dy++) {
        int yy = y + dy - 1;
        if ((unsigned)yy >= 32u) continue;
#pragma unroll
        for (int dx = 0; dx < 3; dx++) {
            int xx = x + dx - 1;
            if ((unsigned)xx >= 32u) continue;
            s += A1[base + (size_t)(yy * 32 + xx) * NPROJ + 1536 + c] * cw[c * 9 + dy * 3 + dx];
        }
    }
    xc[(size_t)r * CONVD + c] = s / (1.f + __expf(-s));
}

// ---------------- selective scan: one warp per (dir, b, h) ----------------
struct Fetch { float dt, B0, B1, C0, C1; float2 x; };

__global__ void __launch_bounds__(128)
scan_kernel(const float* __restrict__ A1, const float* __restrict__ xc,
            float* __restrict__ yall)
{
    __shared__ ulonglong2 sSC[4][64];
    const int lane = threadIdx.x & 31, ws = threadIdx.x >> 5;
    const int W = blockIdx.x * 4 + ws;             // 0..3071
    const int k = W / 768, rem = W % 768;
    const int b = rem / 24, h = rem % 24;
    const int g = k >> 1, rev = k & 1;
    const size_t rbase = (size_t)b * 1024;
    float* yout = yall + (size_t)k * ROWS * DINNER;

    ull hst[64];
#pragma unroll
    for (int n = 0; n < 64; n++) hst[n] = 0ull;

    Fetch cur, nxt;
    {
        int tt = rev ? 1023 : 0;
        size_t r = rbase + tt;
        const float* xr = &xc[r * CONVD];
        cur.dt = __ldg(&A1[r * NPROJ + 3328 + k * 24 + h]);
        cur.B0 = __ldg(&xr[1536 + g * 64 + lane]);
        cur.B1 = __ldg(&xr[1536 + g * 64 + lane + 32]);
        cur.C0 = __ldg(&xr[1664 + g * 64 + lane]);
        cur.C1 = __ldg(&xr[1664 + g * 64 + lane + 32]);
        cur.x  = *(const float2*)&xr[h * 64 + lane * 2];
    }

    for (int t = 0; t < 1024; t++) {
        if (t < 1023) {
            int tt = rev ? 1022 - t : t + 1;
            size_t r = rbase + tt;
            const float* xr = &xc[r * CONVD];
            nxt.dt = __ldg(&A1[r * NPROJ + 3328 + k * 24 + h]);
            nxt.B0 = __ldg(&xr[1536 + g * 64 + lane]);
            nxt.B1 = __ldg(&xr[1536 + g * 64 + lane + 32]);
            nxt.C0 = __ldg(&xr[1664 + g * 64 + lane]);
            nxt.C1 = __ldg(&xr[1664 + g * 64 + lane + 32]);
            nxt.x  = *(const float2*)&xr[h * 64 + lane * 2];
        }
        float dtp = cur.dt > 20.f ? cur.dt : log1pf(__expf(cur.dt));
        float a = __expf(-dtp);
        __syncwarp();
        sSC[ws][lane]      = make_ulonglong2(pack2(dtp * cur.B0), pack2(cur.C0));
        sSC[ws][lane + 32] = make_ulonglong2(pack2(dtp * cur.B1), pack2(cur.C1));
        __syncwarp();

        ull a2 = pack2(a);
        ull x2;
        asm("mov.b64 %0,{%1,%2};" : "=l"(x2)
            : "r"(__float_as_uint(cur.x.x)), "r"(__float_as_uint(cur.x.y)));
        ull y0 = 0ull, y1 = 0ull;
#pragma unroll
        for (int n = 0; n < 64; n += 2) {
            ulonglong2 s0 = sSC[ws][n];
            hst[n] = fma2(a2, hst[n], mul2(s0.x, x2));
            y0 = fma2(s0.y, hst[n], y0);
            ulonglong2 s1 = sSC[ws][n + 1];
            hst[n + 1] = fma2(a2, hst[n + 1], mul2(s1.x, x2));
            y1 = fma2(s1.y, hst[n + 1], y1);
        }
        ull ys = add2(y0, y1);
        uint32_t lo, hi;
        asm("mov.b64 {%0,%1},%2;" : "=r"(lo), "=r"(hi) : "l"(ys));
        int tt = rev ? 1023 - t : t;
        *(float2*)&yout[(rbase + tt) * DINNER + h * 64 + lane * 2] =
            make_float2(__uint_as_float(lo), __uint_as_float(hi));
        if (t < 1023) cur = nxt;
    }
}

// ---------------- sum 4 dirs + gate (silu(z)) + RMSNorm -> bf16 split ----------------
__global__ void __launch_bounds__(256)
gate_rms(const float* __restrict__ A1, const float* __restrict__ yall,
         const float* __restrict__ nw,
         __nv_bfloat16* __restrict__ Yh, __nv_bfloat16* __restrict__ Yl)
{
    __shared__ float red[8];
    __shared__ float s_scale;
    const int r = blockIdx.x, tid = threadIdx.x;
    const float* y0 = yall + (size_t)r * DINNER;
    const float* y1 = y0 + (size_t)ROWS * DINNER;
    const float* y2 = y1 + (size_t)ROWS * DINNER;
    const float* y3 = y2 + (size_t)ROWS * DINNER;

    float v[6]; float ss = 0.f;
#pragma unroll
    for (int i = 0; i < 6; i++) {
        int d = tid + i * 256;
        float y = y0[d] + y1[d] + y2[d] + y3[d];
        float z = A1[(size_t)r * NPROJ + d];
        float zs = z / (1.f + __expf(-z));
        v[i] = y * zs;
        ss += v[i] * v[i];
    }
#pragma unroll
    for (int o = 16; o; o >>= 1) ss += __shfl_xor_sync(0xffffffffu, ss, o);
    if ((tid & 31) == 0) red[tid >> 5] = ss;
    __syncthreads();
    if (tid == 0) {
        float t = 0.f;
#pragma unroll
        for (int i = 0; i < 8; i++) t += red[i];
        s_scale = rsqrtf(t / 1536.f + 1e-5f);
    }
    __syncthreads();
    float scale = s_scale;
#pragma unroll
    for (int i = 0; i < 6; i++) {
        int d = tid + i * 256;
        float yn = v[i] * scale * nw[d];
        __nv_bfloat16 hv = __float2bfloat16(yn);
        size_t idx = (size_t)r * DINNER + d;
        Yh[idx] = hv;
        Yl[idx] = __float2bfloat16(yn - __bfloat162float(hv));
    }
}

// ---------------- host launcher ----------------
extern "C" void kernel_launch(void* const* d_in, const int* in_sizes, int n_in,
                              void* d_out, int out_size)
{
    const float* u      = (const float*)d_in[0];
    const float* w_in   = (const float*)d_in[1];
    const float* conv_w = (const float*)d_in[2];
    const float* conv_b = (const float*)d_in[3];
    const float* norm_w = (const float*)d_in[4];
    const float* w_out  = (const float*)d_in[5];

    void *pA1, *pxc, *py, *pUh, *pUl, *pWih, *pWil, *pWoh, *pWol, *pYh, *pYl;
    cudaGetSymbolAddress(&pA1, g_A1);
    cudaGetSymbolAddress(&pxc, g_xc);
    cudaGetSymbolAddress(&py,  g_y);
    cudaGetSymbolAddress(&pUh, g_Uh);   cudaGetSymbolAddress(&pUl, g_Ul);
    cudaGetSymbolAddress(&pWih, g_Wih); cudaGetSymbolAddress(&pWil, g_Wil);
    cudaGetSymbolAddress(&pWoh, g_Woh); cudaGetSymbolAddress(&pWol, g_Wol);
    cudaGetSymbolAddress(&pYh, g_Yh);   cudaGetSymbolAddress(&pYl, g_Yl);

    cudaFuncSetAttribute(gemm_bf16x3, cudaFuncAttributeMaxDynamicSharedMemorySize, GEMM_SMEM);

    size_t nu  = (size_t)ROWS * DMODEL;
    size_t nwi = (size_t)NPROJ * DMODEL;
    size_t nwo = (size_t)DMODEL * DINNER;
    cvt_kernel<<<(unsigned)((nu  + 255) / 256), 256>>>(u,     (__nv_bfloat16*)pUh,  (__nv_bfloat16*)pUl,  nu);
    cvt_kernel<<<(unsigned)((nwi + 255) / 256), 256>>>(w_in,  (__nv_bfloat16*)pWih, (__nv_bfloat16*)pWil, nwi);
    cvt_kernel<<<(unsigned)((nwo + 255) / 256), 256>>>(w_out, (__nv_bfloat16*)pWoh, (__nv_bfloat16*)pWol, nwo);

    // in-projection: (32768 x 3424) = u (32768 x 768) @ w_in^T
    gemm_bf16x3<<<dim3(27, 256), 256, GEMM_SMEM>>>(
        (__nv_bfloat16*)pUh, (__nv_bfloat16*)pUl,
        (__nv_bfloat16*)pWih, (__nv_bfloat16*)pWil,
        (float*)pA1, ROWS, NPROJ, DMODEL);

    conv_silu<<<dim3(7, ROWS), 256>>>((const float*)pA1, conv_w, conv_b, (float*)pxc);

    scan_kernel<<<768, 128>>>((const float*)pA1, (const float*)pxc, (float*)py);

    gate_rms<<<ROWS, 256>>>((const float*)pA1, (const float*)py, norm_w,
                            (__nv_bfloat16*)pYh, (__nv_bfloat16*)pYl);

    // out-projection: (32768 x 768) = yn (32768 x 1536) @ w_out^T
    gemm_bf16x3<<<dim3(6, 256), 256, GEMM_SMEM>>>(
        (__nv_bfloat16*)pYh, (__nv_bfloat16*)pYl,
        (__nv_bfloat16*)pWoh, (__nv_bfloat16*)pWol,
        (float*)d_out, ROWS, DMODEL, DINNER);
}

// round 9
// speedup vs baseline: 1.1748x; 1.0058x over previous
#include <cuda_runtime.h>
#include <cuda_bf16.h>
#include <cstdint>
#include <cstddef>

#define ROWS   32768
#define NPROJ  3424
#define CONVD  1792
#define DINNER 1536
#define DMODEL 768

typedef unsigned long long ull;

// ---------------- scratch (device globals; no runtime allocation) ----------------
__device__ float g_A1[(size_t)ROWS * NPROJ];            // zxBCdt
__device__ float g_xc[(size_t)ROWS * CONVD];            // conv+silu output
__device__ float g_y [(size_t)4 * ROWS * DINNER];       // per-direction scan outputs
__device__ __nv_bfloat16 g_Uh [(size_t)ROWS * DMODEL];
__device__ __nv_bfloat16 g_Ul [(size_t)ROWS * DMODEL];
__device__ __nv_bfloat16 g_Wih[(size_t)NPROJ * DMODEL];
__device__ __nv_bfloat16 g_Wil[(size_t)NPROJ * DMODEL];
__device__ __nv_bfloat16 g_Woh[(size_t)DMODEL * DINNER];
__device__ __nv_bfloat16 g_Wol[(size_t)DMODEL * DINNER];
__device__ __nv_bfloat16 g_Yh [(size_t)ROWS * DINNER];
__device__ __nv_bfloat16 g_Yl [(size_t)ROWS * DINNER];

// ---------------- packed f32x2 helpers ----------------
__device__ __forceinline__ ull fma2(ull a, ull b, ull c) {
    ull d; asm("fma.rn.f32x2 %0,%1,%2,%3;" : "=l"(d) : "l"(a), "l"(b), "l"(c)); return d;
}
__device__ __forceinline__ ull mul2(ull a, ull b) {
    ull d; asm("mul.rn.f32x2 %0,%1,%2;" : "=l"(d) : "l"(a), "l"(b)); return d;
}
__device__ __forceinline__ ull add2(ull a, ull b) {
    ull d; asm("add.rn.f32x2 %0,%1,%2;" : "=l"(d) : "l"(a), "l"(b)); return d;
}
__device__ __forceinline__ ull pack2(float x) {
    unsigned r = __float_as_uint(x);
    ull d; asm("mov.b64 %0,{%1,%1};" : "=l"(d) : "r"(r)); return d;
}
__device__ __forceinline__ ull pack2f(float x, float y) {
    ull d; asm("mov.b64 %0,{%1,%2};" : "=l"(d)
               : "r"(__float_as_uint(x)), "r"(__float_as_uint(y))); return d;
}

// ---------------- fp32 -> bf16 hi/lo split ----------------
__global__ void cvt_kernel(const float* __restrict__ s,
                           __nv_bfloat16* __restrict__ hi,
                           __nv_bfloat16* __restrict__ lo, size_t n) {
    size_t i = (size_t)blockIdx.x * blockDim.x + threadIdx.x;
    if (i >= n) return;
    float v = s[i];
    __nv_bfloat16 h = __float2bfloat16(v);
    hi[i] = h;
    lo[i] = __float2bfloat16(v - __bfloat162float(h));
}

// =========== tensor-core GEMM (mma.sync): C[M,N] = A[M,K] * B[N,K]^T ===========
// 128x128 CTA tile, KC=32 chunks, 2-stage double buffer, 2 CTAs/SM,
// 3-pass bf16 split (AhBh + AlBh + AhBl), fp32 accumulate.

#define SK 40                            // smem row stride in halves (32 + 8 pad)
#define AR_BYTES (128 * SK * 2)          // 10240 per array
#define STG_BYTES (4 * AR_BYTES)         // 40960 per stage (Ah|Al|Bh|Bl)
#define GEMM_SMEM (2 * STG_BYTES)        // 81920

__device__ __forceinline__ void mma_bf16(float* c, const uint32_t* a, const uint32_t* b) {
    asm volatile("mma.sync.aligned.m16n8k16.row.col.f32.bf16.bf16.f32 "
                 "{%0,%1,%2,%3},{%4,%5,%6,%7},{%8,%9},{%0,%1,%2,%3};"
                 : "+f"(c[0]), "+f"(c[1]), "+f"(c[2]), "+f"(c[3])
                 : "r"(a[0]), "r"(a[1]), "r"(a[2]), "r"(a[3]), "r"(b[0]), "r"(b[1]));
}
__device__ __forceinline__ void ldsm4(uint32_t* r, const __nv_bfloat16* p) {
    uint32_t a = (uint32_t)__cvta_generic_to_shared(p);
    asm volatile("ldmatrix.sync.aligned.m8n8.x4.shared.b16 {%0,%1,%2,%3},[%4];"
                 : "=r"(r[0]), "=r"(r[1]), "=r"(r[2]), "=r"(r[3]) : "r"(a));
}
__device__ __forceinline__ void ldsm2(uint32_t* r, const __nv_bfloat16* p) {
    uint32_t a = (uint32_t)__cvta_generic_to_shared(p);
    asm volatile("ldmatrix.sync.aligned.m8n8.x2.shared.b16 {%0,%1},[%2];"
                 : "=r"(r[0]), "=r"(r[1]) : "r"(a));
}
__device__ __forceinline__ void cpa16(uint32_t dst, const void* src, int sz) {
    asm volatile("cp.async.cg.shared.global [%0], [%1], 16, %2;"
                 :: "r"(dst), "l"(src), "r"(sz));
}

// load one KC=32 chunk into a stage.  256 threads, 2 slots per array each.
__device__ __forceinline__ void load_stage(uint32_t sbase,
        const __nv_bfloat16* __restrict__ Ah, const __nv_bfloat16* __restrict__ Al,
        const __nv_bfloat16* __restrict__ Bh, const __nv_bfloat16* __restrict__ Bl,
        int mBase, int nBase, int N, int K, int k0, int tid)
{
#pragma unroll
    for (int i = 0; i < 2; i++) {
        int idx = tid + i * 256;          // 0..511
        int row = idx >> 2, seg = idx & 3;
        uint32_t so = (uint32_t)(row * (SK * 2) + seg * 16);
        size_t aoff = (size_t)(mBase + row) * K + k0 + seg * 8;
        cpa16(sbase + so,                Ah + aoff, 16);
        cpa16(sbase + AR_BYTES + so,     Al + aoff, 16);
        int brow = nBase + row;
        int ok = (brow < N) ? 16 : 0;
        size_t boff = (size_t)(ok ? brow : 0) * K + k0 + seg * 8;
        cpa16(sbase + 2 * AR_BYTES + so, Bh + boff, ok);
        cpa16(sbase + 3 * AR_BYTES + so, Bl + boff, ok);
    }
    asm volatile("cp.async.commit_group;");
}

__global__ void __launch_bounds__(256, 2)
gemm_bf16x3(const __nv_bfloat16* __restrict__ Ah, const __nv_bfloat16* __restrict__ Al,
            const __nv_bfloat16* __restrict__ Bh, const __nv_bfloat16* __restrict__ Bl,
            float* __restrict__ C, int M, int N, int K)
{
    extern __shared__ char smem[];
    uint32_t sb = (uint32_t)__cvta_generic_to_shared(smem);
    const int tid = threadIdx.x, lane = tid & 31, warp = tid >> 5;
    const int wm = warp >> 2, wn = warp & 3;       // 2x4 warp grid; warp tile 64m x 32n
    const int g = lane >> 2, tg = lane & 3;
    const int mBase = blockIdx.y * 128, nBase = blockIdx.x * 128;

    float acc[4][4][4];
#pragma unroll
    for (int mi = 0; mi < 4; mi++)
#pragma unroll
        for (int ni = 0; ni < 4; ni++)
#pragma unroll
            for (int q = 0; q < 4; q++) acc[mi][ni][q] = 0.f;

    const int KT = K / 32;

    // prologue: both stages in flight
    load_stage(sb,             Ah, Al, Bh, Bl, mBase, nBase, N, K, 0,  tid);
    load_stage(sb + STG_BYTES, Ah, Al, Bh, Bl, mBase, nBase, N, K, 32, tid);

    for (int kt = 0; kt < KT; kt++) {
        const int s = kt & 1;
        if (kt + 1 < KT) asm volatile("cp.async.wait_group 1;" ::: "memory");
        else             asm volatile("cp.async.wait_group 0;" ::: "memory");
        __syncthreads();

        const __nv_bfloat16* sAh = (const __nv_bfloat16*)(smem + s * STG_BYTES);
        const __nv_bfloat16* sAl = (const __nv_bfloat16*)(smem + s * STG_BYTES + AR_BYTES);
        const __nv_bfloat16* sBh = (const __nv_bfloat16*)(smem + s * STG_BYTES + 2 * AR_BYTES);
        const __nv_bfloat16* sBl = (const __nv_bfloat16*)(smem + s * STG_BYTES + 3 * AR_BYTES);

#pragma unroll
        for (int kk = 0; kk < 32; kk += 16) {
            uint32_t aH[4][4], bX[4][2];
            // pass 1: Ah * Bh
#pragma unroll
            for (int mi = 0; mi < 4; mi++) {
                int off = (wm * 64 + mi * 16 + (lane & 15)) * SK + kk + ((lane >> 4) << 3);
                ldsm4(aH[mi], &sAh[off]);
            }
#pragma unroll
            for (int ni = 0; ni < 4; ni++) {
                int off = (wn * 32 + ni * 8 + (lane & 7)) * SK + kk + (((lane >> 3) & 1) << 3);
                ldsm2(bX[ni], &sBh[off]);
            }
#pragma unroll
            for (int mi = 0; mi < 4; mi++)
#pragma unroll
                for (int ni = 0; ni < 4; ni++) mma_bf16(acc[mi][ni], aH[mi], bX[ni]);

            // pass 2: Al * Bh (reuse bX = Bh)
            {
                uint32_t aL[4][4];
#pragma unroll
                for (int mi = 0; mi < 4; mi++) {
                    int off = (wm * 64 + mi * 16 + (lane & 15)) * SK + kk + ((lane >> 4) << 3);
                    ldsm4(aL[mi], &sAl[off]);
                }
#pragma unroll
                for (int mi = 0; mi < 4; mi++)
#pragma unroll
                    for (int ni = 0; ni < 4; ni++) mma_bf16(acc[mi][ni], aL[mi], bX[ni]);
            }

            // pass 3: Ah * Bl (reuse bX regs for Bl)
#pragma unroll
            for (int ni = 0; ni < 4; ni++) {
                int off = (wn * 32 + ni * 8 + (lane & 7)) * SK + kk + (((lane >> 3) & 1) << 3);
                ldsm2(bX[ni], &sBl[off]);
            }
#pragma unroll
            for (int mi = 0; mi < 4; mi++)
#pragma unroll
                for (int ni = 0; ni < 4; ni++) mma_bf16(acc[mi][ni], aH[mi], bX[ni]);
        }
        __syncthreads();

        if (kt + 2 < KT) {
            load_stage(sb + s * STG_BYTES,
                       Ah, Al, Bh, Bl, mBase, nBase, N, K, (kt + 2) * 32, tid);
        }
    }

    // ---- epilogue ----
#pragma unroll
    for (int mi = 0; mi < 4; mi++)
#pragma unroll
        for (int ni = 0; ni < 4; ni++) {
            int row = mBase + wm * 64 + mi * 16 + g;
            int col = nBase + wn * 32 + ni * 8 + tg * 2;
            if (col < N) {
                *(float2*)&C[(size_t)row * N + col] =
                    make_float2(acc[mi][ni][0], acc[mi][ni][1]);
                *(float2*)&C[(size_t)(row + 8) * N + col] =
                    make_float2(acc[mi][ni][2], acc[mi][ni][3]);
            }
        }
}

// ---------------- depthwise 3x3 conv + bias + SiLU ----------------
__global__ void conv_silu(const float* __restrict__ A1, const float* __restrict__ cw,
                          const float* __restrict__ cb, float* __restrict__ xc)
{
    int c = blockIdx.x * 256 + threadIdx.x;   // 0..1791
    int r = blockIdx.y;                        // 0..32767
    int pos = r & 1023;
    int y = pos >> 5, x = pos & 31;
    size_t base = (size_t)(r - pos) * NPROJ;
    float s = cb[c];
#pragma unroll
    for (int dy = 0; dy < 3; dy++) {
        int yy = y + dy - 1;
        if ((unsigned)yy >= 32u) continue;
#pragma unroll
        for (int dx = 0; dx < 3; dx++) {
            int xx = x + dx - 1;
            if ((unsigned)xx >= 32u) continue;
            s += A1[base + (size_t)(yy * 32 + xx) * NPROJ + 1536 + c] * cw[c * 9 + dy * 3 + dx];
        }
    }
    xc[(size_t)r * CONVD + c] = s / (1.f + __expf(-s));
}

// ---------------- selective scan: 2 warps per (dir,b,h), split over P ----------------
// Lane owns one p; state h[n][p] packed as 32 f32x2 n-pairs (64 regs).
// y_p = sum_n C_n h_{n,p} is lane-local => warps fully independent.
struct Fetch2 { float dt, x; float2 B2, C2; };

__global__ void __launch_bounds__(256)
scan_kernel(const float* __restrict__ A1, const float* __restrict__ xc,
            float* __restrict__ yall)
{
    __shared__ ulonglong2 sSC[8][32];
    const int lane = threadIdx.x & 31, ws = threadIdx.x >> 5;
    const int W = blockIdx.x * 8 + ws;          // 0..6143
    const int scan = W >> 1, ph = W & 1;        // scan id, p-half
    const int k = scan / 768, rem = scan % 768;
    const int b = rem / 24, h = rem % 24;
    const int g = k >> 1, rev = k & 1;
    const size_t rbase = (size_t)b * 1024;
    float* yout = yall + (size_t)k * ROWS * DINNER;

    ull hst[32];
#pragma unroll
    for (int n = 0; n < 32; n++) hst[n] = 0ull;

    Fetch2 cur, nxt;
    {
        int tt = rev ? 1023 : 0;
        size_t r = rbase + tt;
        const float* xr = &xc[r * CONVD];
        cur.dt = __ldg(&A1[r * NPROJ + 3328 + k * 24 + h]);
        cur.B2 = *(const float2*)&xr[1536 + g * 64 + lane * 2];
        cur.C2 = *(const float2*)&xr[1664 + g * 64 + lane * 2];
        cur.x  = __ldg(&xr[h * 64 + ph * 32 + lane]);
    }

    for (int t = 0; t < 1024; t++) {
        if (t < 1023) {
            int tt = rev ? 1022 - t : t + 1;
            size_t r = rbase + tt;
            const float* xr = &xc[r * CONVD];
            nxt.dt = __ldg(&A1[r * NPROJ + 3328 + k * 24 + h]);
            nxt.B2 = *(const float2*)&xr[1536 + g * 64 + lane * 2];
            nxt.C2 = *(const float2*)&xr[1664 + g * 64 + lane * 2];
            nxt.x  = __ldg(&xr[h * 64 + ph * 32 + lane]);
        }
        float dtp = cur.dt > 20.f ? cur.dt : log1pf(__expf(cur.dt));
        float a = __expf(-dtp);
        __syncwarp();
        sSC[ws][lane] = make_ulonglong2(pack2f(dtp * cur.B2.x, dtp * cur.B2.y),
                                        pack2f(cur.C2.x, cur.C2.y));
        __syncwarp();

        ull a2 = pack2(a);
        ull x2 = pack2(cur.x);
        ull y0 = 0ull, y1 = 0ull;
#pragma unroll
        for (int m = 0; m < 32; m += 2) {
            ulonglong2 s0 = sSC[ws][m];
            hst[m] = fma2(a2, hst[m], mul2(s0.x, x2));
            y0 = fma2(s0.y, hst[m], y0);
            ulonglong2 s1 = sSC[ws][m + 1];
            hst[m + 1] = fma2(a2, hst[m + 1], mul2(s1.x, x2));
            y1 = fma2(s1.y, hst[m + 1], y1);
        }
        ull ys = add2(y0, y1);
        uint32_t lo, hi;
        asm("mov.b64 {%0,%1},%2;" : "=r"(lo), "=r"(hi) : "l"(ys));
        int tt = rev ? 1023 - t : t;
        yout[(rbase + tt) * DINNER + h * 64 + ph * 32 + lane] =
            __uint_as_float(lo) + __uint_as_float(hi);
        if (t < 1023) cur = nxt;
    }
}

// ---------------- sum 4 dirs + gate (silu(z)) + RMSNorm -> bf16 split ----------------
__global__ void __launch_bounds__(256)
gate_rms(const float* __restrict__ A1, const float* __restrict__ yall,
         const float* __restrict__ nw,
         __nv_bfloat16* __restrict__ Yh, __nv_bfloat16* __restrict__ Yl)
{
    __shared__ float red[8];
    __shared__ float s_scale;
    const int r = blockIdx.x, tid = threadIdx.x;
    const float* y0 = yall + (size_t)r * DINNER;
    const float* y1 = y0 + (size_t)ROWS * DINNER;
    const float* y2 = y1 + (size_t)ROWS * DINNER;
    const float* y3 = y2 + (size_t)ROWS * DINNER;

    float v[6]; float ss = 0.f;
#pragma unroll
    for (int i = 0; i < 6; i++) {
        int d = tid + i * 256;
        float y = y0[d] + y1[d] + y2[d] + y3[d];
        float z = A1[(size_t)r * NPROJ + d];
        float zs = z / (1.f + __expf(-z));
        v[i] = y * zs;
        ss += v[i] * v[i];
    }
#pragma unroll
    for (int o = 16; o; o >>= 1) ss += __shfl_xor_sync(0xffffffffu, ss, o);
    if ((tid & 31) == 0) red[tid >> 5] = ss;
    __syncthreads();
    if (tid == 0) {
        float t = 0.f;
#pragma unroll
        for (int i = 0; i < 8; i++) t += red[i];
        s_scale = rsqrtf(t / 1536.f + 1e-5f);
    }
    __syncthreads();
    float scale = s_scale;
#pragma unroll
    for (int i = 0; i < 6; i++) {
        int d = tid + i * 256;
        float yn = v[i] * scale * nw[d];
        __nv_bfloat16 hv = __float2bfloat16(yn);
        size_t idx = (size_t)r * DINNER + d;
        Yh[idx] = hv;
        Yl[idx] = __float2bfloat16(yn - __bfloat162float(hv));
    }
}

// ---------------- host launcher ----------------
extern "C" void kernel_launch(void* const* d_in, const int* in_sizes, int n_in,
                              void* d_out, int out_size)
{
    const float* u      = (const float*)d_in[0];
    const float* w_in   = (const float*)d_in[1];
    const float* conv_w = (const float*)d_in[2];
    const float* conv_b = (const float*)d_in[3];
    const float* norm_w = (const float*)d_in[4];
    const float* w_out  = (const float*)d_in[5];

    void *pA1, *pxc, *py, *pUh, *pUl, *pWih, *pWil, *pWoh, *pWol, *pYh, *pYl;
    cudaGetSymbolAddress(&pA1, g_A1);
    cudaGetSymbolAddress(&pxc, g_xc);
    cudaGetSymbolAddress(&py,  g_y);
    cudaGetSymbolAddress(&pUh, g_Uh);   cudaGetSymbolAddress(&pUl, g_Ul);
    cudaGetSymbolAddress(&pWih, g_Wih); cudaGetSymbolAddress(&pWil, g_Wil);
    cudaGetSymbolAddress(&pWoh, g_Woh); cudaGetSymbolAddress(&pWol, g_Wol);
    cudaGetSymbolAddress(&pYh, g_Yh);   cudaGetSymbolAddress(&pYl, g_Yl);

    cudaFuncSetAttribute(gemm_bf16x3, cudaFuncAttributeMaxDynamicSharedMemorySize, GEMM_SMEM);

    size_t nu  = (size_t)ROWS * DMODEL;
    size_t nwi = (size_t)NPROJ * DMODEL;
    size_t nwo = (size_t)DMODEL * DINNER;
    cvt_kernel<<<(unsigned)((nu  + 255) / 256), 256>>>(u,     (__nv_bfloat16*)pUh,  (__nv_bfloat16*)pUl,  nu);
    cvt_kernel<<<(unsigned)((nwi + 255) / 256), 256>>>(w_in,  (__nv_bfloat16*)pWih, (__nv_bfloat16*)pWil, nwi);
    cvt_kernel<<<(unsigned)((nwo + 255) / 256), 256>>>(w_out, (__nv_bfloat16*)pWoh, (__nv_bfloat16*)pWol, nwo);

    // in-projection: (32768 x 3424) = u (32768 x 768) @ w_in^T
    gemm_bf16x3<<<dim3(27, 256), 256, GEMM_SMEM>>>(
        (__nv_bfloat16*)pUh, (__nv_bfloat16*)pUl,
        (__nv_bfloat16*)pWih, (__nv_bfloat16*)pWil,
        (float*)pA1, ROWS, NPROJ, DMODEL);

    conv_silu<<<dim3(7, ROWS), 256>>>((const float*)pA1, conv_w, conv_b, (float*)pxc);

    scan_kernel<<<768, 256>>>((const float*)pA1, (const float*)pxc, (float*)py);

    gate_rms<<<ROWS, 256>>>((const float*)pA1, (const float*)py, norm_w,
                            (__nv_bfloat16*)pYh, (__nv_bfloat16*)pYl);

    // out-projection: (32768 x 768) = yn (32768 x 1536) @ w_out^T
    gemm_bf16x3<<<dim3(6, 256), 256, GEMM_SMEM>>>(
        (__nv_bfloat16*)pYh, (__nv_bfloat16*)pYl,
        (__nv_bfloat16*)pWoh, (__nv_bfloat16*)pWol,
        (float*)d_out, ROWS, DMODEL, DINNER);
}